// round 9
// baseline (speedup 1.0000x reference)
#include <cuda_runtime.h>
#include <math.h>

#define K 128
#define E 4096
#define M 512
#define NUM_UPDATE 3
#define THRESHOLD 0.05f
#define HOT 8
#define MAXNZ 32
#define NBLK 16                       // e-chunks per step grid
#define NB_TOTAL (NBLK * K)           // 2048 blocks

// ---------------- device scratch ----------------
__device__ __align__(16) unsigned char g_nzpk[E * MAXNZ];
__device__ unsigned char g_cnt[E];
__device__ float4 g_cc[E];                    // (c0, c1, score, 1/d) per e
__device__ float  g_bz[E];                    // beta2 * Zc
__device__ float2 g_a12[(size_t)K * E];       // (uw*beta1, uw*bz)
__device__ float  g_Bc[(size_t)K * E * HOT];  // gathered B, diag/pad zeroed
__device__ __align__(16) float g_dval[E * HOT]; // dv[j_i(e)] per step, pad=0
__device__ float2 g_icf[E];                   // (Ic, tailflag) per step
__device__ float  g_u[K];
__device__ float  g_dv[K];
__device__ int    g_upd[K];
__device__ float  g_partial[K * NBLK];
__device__ unsigned g_done[NUM_UPDATE];

__device__ __forceinline__ float sigm_neg(float x) {
    return __fdividef(1.0f, 1.0f + __expf(x));  // sigmoid(-x)
}

// ---------------- init0: nz lists, constants, dval0, Icf0, u0 ----------------
// grid = E/8 = 512 blocks of 256 (warp per e)
__global__ void init0_kernel(const float* __restrict__ q_kn,
                             const float* __restrict__ U,
                             const int* __restrict__ stu_id,
                             const int* __restrict__ kn_id,
                             const float* __restrict__ gamma_c,
                             const float* __restrict__ dd,
                             const float* __restrict__ score,
                             const float* __restrict__ beta2,
                             const float* __restrict__ gs,
                             const float* __restrict__ A_emb) {
    int tid = threadIdx.x;
    int w = tid >> 5, l = tid & 31;
    int e = blockIdx.x * 8 + w;
    int stu = stu_id[0];

    if (l < HOT) g_dval[e * HOT + l] = 0.0f;
    __syncwarp();

    int base = 0;
    float su = 0.0f;
#pragma unroll
    for (int r = 0; r < 4; r++) {
        int j = r * 32 + l;
        float q = q_kn[(size_t)e * K + j];
        unsigned m = __ballot_sync(0xFFFFFFFFu, q != 0.0f);
        if (q != 0.0f) {
            int pos = base + __popc(m & ((1u << l) - 1u));
            float u0j = U[(size_t)stu * K + j];
            if (pos < MAXNZ) g_nzpk[e * MAXNZ + pos] = (unsigned char)j;
            float dvj = u0j - 0.5f;
            dvj = (fabsf(dvj) > THRESHOLD) ? dvj : 0.0f;
            if (pos < HOT) g_dval[e * HOT + pos] = dvj;
            su += u0j;
        }
        base += __popc(m);
    }
    su += __shfl_xor_sync(0xFFFFFFFFu, su, 16);
    su += __shfl_xor_sync(0xFFFFFFFFu, su, 8);
    su += __shfl_xor_sync(0xFFFFFFFFu, su, 4);
    su += __shfl_xor_sync(0xFFFFFFFFu, su, 2);
    su += __shfl_xor_sync(0xFFFFFFFFu, su, 1);
    if (l == 0) {
        int cnt = base < MAXNZ ? base : MAXNZ;
        g_cnt[e] = (unsigned char)cnt;
        float invd = 1.0f / dd[e];
        float sc   = score[e];
        float x  = (gamma_c[e] * invd) * (sc - 0.5f);
        g_bz[e]  = beta2[e] * (sigm_neg(x) - 0.5f);
        float c0 = A_emb[3 * e + 0] * (1.0f - gs[2 * e + 0])
                 + A_emb[3 * e + 1] * (1.0f - gs[2 * e + 1]);
        float c1 = A_emb[3 * e + 2];
        g_cc[e] = make_float4(c0, c1, sc, invd);
        float t  = sc - su * invd;
        float Ic = sigm_neg(c0 + c1 * __expf(-t * t));
        g_icf[e] = make_float2(Ic, cnt > HOT ? 1.0f : 0.0f);
    }

    if (blockIdx.x == 0) {
        if (tid < NUM_UPDATE) g_done[tid] = 0u;
        if (tid < K) {
            float u0 = U[(size_t)stu * K + tid];
            g_u[tid] = u0;
            float dv = u0 - 0.5f;
            g_dv[tid] = (fabsf(dv) > THRESHOLD) ? dv : 0.0f;
            g_upd[tid] = 0;
        }
        __syncthreads();
        if (tid < K) {
            int kn = kn_id[tid];
            if (kn >= 0 && kn < K) g_upd[kn] = 1;
        }
    }
}

// ---------------- pre: per-step dval + Icf from current g_u ----------------
// grid = 16 blocks of 256; 1 e per thread
__global__ void pre_kernel() {
    __shared__ float s_u[K];
    __shared__ float s_dv[K];
    int tid = threadIdx.x;
    if (tid < K) {
        float u = g_u[tid];
        s_u[tid] = u;
        float dv = u - 0.5f;
        s_dv[tid] = (fabsf(dv) > THRESHOLD) ? dv : 0.0f;
    }
    __syncthreads();

    int e = blockIdx.x * 256 + tid;
    const uint4* pkp = (const uint4*)(g_nzpk + e * MAXNZ);
    uint4 p0 = pkp[0], p1 = pkp[1];
    unsigned pw[8] = {p0.x, p0.y, p0.z, p0.w, p1.x, p1.y, p1.z, p1.w};
    int cnt = g_cnt[e];
    float4 cc = g_cc[e];

    float su = 0.0f;
    float v[HOT];
#pragma unroll
    for (int i = 0; i < HOT; i++) {
        int j = (pw[i >> 2] >> ((i & 3) * 8)) & 0xFF;
        bool valid = i < cnt;
        v[i] = valid ? s_dv[j] : 0.0f;
        su += valid ? s_u[j] : 0.0f;
    }
    for (int i = HOT; i < cnt; i++) {
        int j = (pw[i >> 2] >> ((i & 3) * 8)) & 0xFF;
        su += s_u[j];
    }
    float4* dst = (float4*)(g_dval + e * HOT);
    dst[0] = make_float4(v[0], v[1], v[2], v[3]);
    dst[1] = make_float4(v[4], v[5], v[6], v[7]);

    float t  = cc.z - su * cc.w;
    float Ic = sigm_neg(cc.x + cc.y * __expf(-t * t));
    g_icf[e] = make_float2(Ic, cnt > HOT ? 1.0f : 0.0f);
}

// ---------------- big step kernel ----------------
// grid = (NBLK, K) = (16, 128) = 2048 blocks of 256; 1 pair per thread.
// GATHER (step 0): gathers B, computes dot, writes Bc + a12.
// !GATHER (steps 1,2): pure streaming over Bc/dval/a12/icf.
template <bool GATHER>
__global__ __launch_bounds__(256) void big_kernel(const float* __restrict__ Bm,
                                                  const float* __restrict__ beta1,
                                                  const float* __restrict__ W,
                                                  const float* __restrict__ user,
                                                  float* __restrict__ out,
                                                  int step) {
    int k = blockIdx.y;
    size_t kE = (size_t)k * E;
    int tid = threadIdx.x;
    int e = blockIdx.x * 256 + tid;

    float dot = 0.0f;
    float2 a, icf;
    bool tail;

    if (GATHER) {
        uint2 pk = *(const uint2*)(g_nzpk + e * MAXNZ);
        int cnt  = g_cnt[e];
        icf = g_icf[e];
        const float4* dp = (const float4*)(g_dval + e * HOT);
        float4 d0 = dp[0], d1 = dp[1];
        float dval[HOT] = {d0.x, d0.y, d0.z, d0.w, d1.x, d1.y, d1.z, d1.w};
        const float* __restrict__ Brow = Bm + (kE + e) * K;
        unsigned pw0 = pk.x, pw1 = pk.y;
        float bc[HOT];
#pragma unroll
        for (int i = 0; i < HOT; i++) {
            int j = ((i < 4 ? pw0 : pw1) >> ((i & 3) * 8)) & 0xFF;
            bool act = (i < cnt) && (j != k);
            bc[i] = act ? __ldg(Brow + j) : 0.0f;
            dot += bc[i] * dval[i];
        }
        float4* dst = (float4*)(g_Bc + (kE + e) * HOT);
        dst[0] = make_float4(bc[0], bc[1], bc[2], bc[3]);
        dst[1] = make_float4(bc[4], bc[5], bc[6], bc[7]);
        float uw = user[kE + e] * W[kE + e];
        a = make_float2(uw * beta1[kE + e], uw * g_bz[e]);
        g_a12[kE + e] = a;
        tail = cnt > HOT;
    } else {
        const float4* bc = (const float4*)(g_Bc + (kE + e) * HOT);
        const float4* dp = (const float4*)(g_dval + e * HOT);
        float4 b0 = bc[0], b1 = bc[1];
        float4 d0 = dp[0], d1 = dp[1];
        a   = g_a12[kE + e];
        icf = g_icf[e];
        dot = b0.x * d0.x + b0.y * d0.y + b0.z * d0.z + b0.w * d0.w
            + b1.x * d1.x + b1.y * d1.y + b1.z * d1.z + b1.w * d1.w;
        tail = icf.y != 0.0f;
    }

    if (tail) {   // rare: finish dot with direct gather
        const uint4* pkp = (const uint4*)(g_nzpk + e * MAXNZ);
        uint4 p0 = pkp[0], p1 = pkp[1];
        unsigned pw[8] = {p0.x, p0.y, p0.z, p0.w, p1.x, p1.y, p1.z, p1.w};
        int cnt = g_cnt[e];
        const float* __restrict__ Brow = Bm + (kE + e) * K;
        for (int i = HOT; i < cnt; i++) {
            int j = (pw[i >> 2] >> ((i & 3) * 8)) & 0xFF;
            if (j != k) dot += __ldg(Brow + j) * g_dv[j];
        }
    }

    float gkc = sigm_neg(dot) - 1.0f;
    float acc = icf.x * (a.x * gkc + a.y);

    // deterministic block reduction
    __shared__ float warpacc[8];
    int w = tid >> 5, l = tid & 31;
    acc += __shfl_xor_sync(0xFFFFFFFFu, acc, 16);
    acc += __shfl_xor_sync(0xFFFFFFFFu, acc, 8);
    acc += __shfl_xor_sync(0xFFFFFFFFu, acc, 4);
    acc += __shfl_xor_sync(0xFFFFFFFFu, acc, 2);
    acc += __shfl_xor_sync(0xFFFFFFFFu, acc, 1);
    if (l == 0) warpacc[w] = acc;
    __syncthreads();

    __shared__ bool is_last;
    if (tid == 0) {
        float s = 0.0f;
#pragma unroll
        for (int i = 0; i < 8; i++) s += warpacc[i];
        g_partial[k * NBLK + blockIdx.x] = s;
        __threadfence();
        unsigned t2 = atomicAdd(&g_done[step], 1u);
        is_last = (t2 == (unsigned)(NB_TOTAL - 1));
    }
    __syncthreads();
    if (!is_last) return;
    __threadfence();

    // ---- tiny fused epilogue (one block): u update + diff norm + outputs ----
    __shared__ float red[K];
    if (tid < K) {
        float s = 0.0f;
#pragma unroll
        for (int c = 0; c < NBLK; c++) s += g_partial[tid * NBLK + c];
        float u_old = g_u[tid];
        float u_new = sigm_neg(s);
        float un = g_upd[tid] ? u_new : u_old;
        float ddf = un - u_old;
        red[tid] = ddf * ddf;
        g_u[tid] = un;
        float dvn = un - 0.5f;
        g_dv[tid] = (fabsf(dvn) > THRESHOLD) ? dvn : 0.0f;
        if (step == NUM_UPDATE - 2) out[K + tid] = un;  // state_2nd_last
        if (step == NUM_UPDATE - 1) out[tid]     = un;  // state_last
    }
    __syncthreads();
#pragma unroll
    for (int off = 64; off > 0; off >>= 1) {
        if (tid < off && tid + off < K) red[tid] += red[tid + off];
        __syncthreads();
    }
    if (tid == 0) out[2 * K + M + step] = sqrtf(red[0]);
}

// ---------------- final predict ----------------
__global__ void predict_kernel(const float* __restrict__ dd,
                               const float* __restrict__ alpha,
                               const float* __restrict__ gamma_e,
                               const int* __restrict__ ex_id,
                               float* __restrict__ out) {
    __shared__ float s_u[K];
    int tid = threadIdx.x;
    if (tid < K) s_u[tid] = g_u[tid];
    __syncthreads();

    int m = blockIdx.x * 256 + tid;
    if (m < M) {
        int e = ex_id[m];
        const uint4* pkp = (const uint4*)(g_nzpk + e * MAXNZ);
        uint4 p0 = pkp[0], p1 = pkp[1];
        unsigned pw[8] = {p0.x, p0.y, p0.z, p0.w, p1.x, p1.y, p1.z, p1.w};
        int cnt = g_cnt[e];
        float accv = 0.0f;
        for (int i = 0; i < cnt; i++) {
            int j = (pw[i >> 2] >> ((i & 3) * 8)) & 0xFF;
            accv += s_u[j];
        }
        float Ukse = accv / dd[e] - 0.5f;
        out[2 * K + m] = sigm_neg(alpha[e] * Ukse + gamma_e[e]);
    }
}

// ---------------- launch ----------------
extern "C" void kernel_launch(void* const* d_in, const int* in_sizes, int n_in,
                              void* d_out, int out_size) {
    const float* U       = (const float*)d_in[0];
    const float* W       = (const float*)d_in[1];
    const float* beta1   = (const float*)d_in[2];
    const float* beta2   = (const float*)d_in[3];
    const float* Bm      = (const float*)d_in[4];
    const float* gs      = (const float*)d_in[5];
    const float* A_emb   = (const float*)d_in[6];
    const float* gamma_c = (const float*)d_in[7];
    const float* gamma_e = (const float*)d_in[8];
    const float* alpha   = (const float*)d_in[9];
    const float* score   = (const float*)d_in[10];
    const float* user    = (const float*)d_in[11];
    const float* q_kn    = (const float*)d_in[12];
    const float* d       = (const float*)d_in[13];
    const int*   stu_id  = (const int*)d_in[14];
    const int*   kn_id   = (const int*)d_in[15];
    const int*   ex_id   = (const int*)d_in[16];
    float* out = (float*)d_out;

    init0_kernel<<<E / 8, 256>>>(q_kn, U, stu_id, kn_id, gamma_c, d, score,
                                 beta2, gs, A_emb);
    big_kernel<true><<<dim3(NBLK, K), 256>>>(Bm, beta1, W, user, out, 0);
    pre_kernel<<<16, 256>>>();
    big_kernel<false><<<dim3(NBLK, K), 256>>>(Bm, beta1, W, user, out, 1);
    pre_kernel<<<16, 256>>>();
    big_kernel<false><<<dim3(NBLK, K), 256>>>(Bm, beta1, W, user, out, 2);
    predict_kernel<<<(M + 255) / 256, 256>>>(d, alpha, gamma_e, ex_id, out);
}